// round 11
// baseline (speedup 1.0000x reference)
#include <cuda_runtime.h>
#include <cuda_fp16.h>
#include <math.h>
#include <cstdint>

// B=128, N=NONGT=36, D=1024, H=16, DG=64, PE=64
#define GM 4608      // rows = B*N
#define GN 3072      // cols = 3*1024  [q|k|vproj]
#define GK 1024      // inner dim
#define KP 1024      // fp16 K (single term Ah @ Bh)
#define BM 128
#define BN 128
#define BK 64
#define NK (KP / BK)   // 16
#define STG 32768      // stage stride: A 16KB + B 16KB
#define NSTAGE 3

// ---------------- device scratch ----------------
__device__ __align__(16) __half g_Ah[(size_t)GM * KP];   // 9.4 MB
__device__ __align__(16) __half g_Bh[(size_t)GN * KP];   // 6.3 MB  [N,K] K-major
__device__ __align__(16) float g_bcat[GN];
__device__ __align__(16) float g_qkv[(size_t)GM * GN];   // 56.6 MB
__device__ __align__(16) float g_pre[4608 * 16 * 36];    // 10.6 MB  pre[b,n][h][m]

// ---------------- helpers ----------------
__device__ __forceinline__ uint32_t smem_u32(const void* p) {
    uint32_t a;
    asm("{ .reg .u64 t; cvta.to.shared.u64 t, %1; cvt.u32.u64 %0, t; }" : "=r"(a) : "l"(p));
    return a;
}
__device__ __forceinline__ void cp16(uint32_t d, const void* s) {
    asm volatile("cp.async.cg.shared.global [%0], [%1], 16;" :: "r"(d), "l"(s));
}

// ---------------- K0a: A fp32 -> fp16 ----------------
__global__ __launch_bounds__(256) void conv_A(const float* __restrict__ A) {
    int i = blockIdx.x * 256 + threadIdx.x;
    float4 v = ((const float4*)A)[i];
    __half2 h01 = __halves2half2(__float2half_rn(v.x), __float2half_rn(v.y));
    __half2 h23 = __halves2half2(__float2half_rn(v.z), __float2half_rn(v.w));
    size_t base = (size_t)i * 4;
    *(__half2*)&g_Ah[base] = h01; *(__half2*)&g_Ah[base + 2] = h23;
}

// ---------------- K0b: weights -> fp16 ----------------
__global__ __launch_bounds__(256) void conv_B(const float* __restrict__ Wq,
                                              const float* __restrict__ Wk,
                                              const float* __restrict__ Wout) {
    int i = blockIdx.x * 256 + threadIdx.x;
    int row = i >> 8;
    int c4 = (i & 255) << 2;
    const float* src = (row < 1024) ? (Wq + (size_t)row * 1024)
                     : (row < 2048) ? (Wk + (size_t)(row - 1024) * 1024)
                                    : (Wout + (size_t)(row - 2048) * 1024);
    float4 v = *(const float4*)(src + c4);
    __half2 h01 = __halves2half2(__float2half_rn(v.x), __float2half_rn(v.y));
    __half2 h23 = __halves2half2(__float2half_rn(v.z), __float2half_rn(v.w));
    size_t base = (size_t)row * KP + c4;
    *(__half2*)&g_Bh[base] = h01; *(__half2*)&g_Bh[base + 2] = h23;
}

__global__ void fill_bcat(const float* __restrict__ bq, const float* __restrict__ bk) {
    int n = blockIdx.x * 256 + threadIdx.x;
    float v = 0.f;
    if (n < 1024) v = bq[n];
    else if (n < 2048) v = bk[n - 1024];
    g_bcat[n] = v;
}

// ---------------- K1: HMMA GEMM  qkv = A @ B^T + bcat ----------------
__device__ __forceinline__ void load_tile(uint32_t base, const __half* Ag, const __half* Bg, int t) {
#pragma unroll
    for (int i = 0; i < 4; i++) {
        int u = t + i * 256;
        int row = u >> 3, k = u & 7;
        uint32_t sw = row * 128 + ((k ^ (row & 7)) << 4);
        cp16(base + sw, (const char*)(Ag + (size_t)row * KP) + k * 16);
        cp16(base + 16384 + sw, (const char*)(Bg + (size_t)row * KP) + k * 16);
    }
    asm volatile("cp.async.commit_group;" ::: "memory");
}

__global__ __launch_bounds__(256, 2) void gemm_hmma() {
    extern __shared__ char smem[];
    uint32_t sb = smem_u32(smem);
    int t = threadIdx.x, lane = t & 31, wid = t >> 5;
    int bm = blockIdx.y * BM, bn = blockIdx.x * BN;
    int wm = wid >> 1, wn = wid & 1;

    const __half* Ag = g_Ah + (size_t)bm * KP;
    const __half* Bg = g_Bh + (size_t)bn * KP;

    float acc[2][8][4];
#pragma unroll
    for (int mt = 0; mt < 2; mt++)
#pragma unroll
        for (int nt = 0; nt < 8; nt++)
#pragma unroll
            for (int j = 0; j < 4; j++) acc[mt][nt][j] = 0.f;

    int a_row = wm * 32 + (lane & 7) + ((lane >> 3) & 1) * 8;   // + mt*16
    int a_ch  = (lane >> 4);                                     // + ks*2
    int b_row = wn * 64 + (lane & 7) + ((lane >> 4) & 1) * 8;   // + ntp*16
    int b_ch  = (lane >> 3) & 1;                                 // + ks*2

    load_tile(sb, Ag, Bg, t);
    load_tile(sb + STG, Ag + BK, Bg + BK, t);

    for (int kt = 0; kt < NK; kt++) {
        if (kt + 2 < NK) {
            load_tile(sb + ((kt + 2) % NSTAGE) * STG,
                      Ag + (size_t)(kt + 2) * BK, Bg + (size_t)(kt + 2) * BK, t);
            asm volatile("cp.async.wait_group 2;" ::: "memory");
        } else {
            asm volatile("cp.async.wait_group 0;" ::: "memory");
        }
        __syncthreads();

        uint32_t base = sb + (kt % NSTAGE) * STG;
#pragma unroll
        for (int ks = 0; ks < 4; ks++) {
            uint32_t af[2][4];
#pragma unroll
            for (int mt = 0; mt < 2; mt++) {
                int r = a_row + mt * 16;
                uint32_t ad = base + r * 128 + (((ks * 2 + a_ch) ^ (r & 7)) << 4);
                asm volatile("ldmatrix.sync.aligned.m8n8.x4.shared.b16 {%0,%1,%2,%3}, [%4];"
                             : "=r"(af[mt][0]), "=r"(af[mt][1]), "=r"(af[mt][2]), "=r"(af[mt][3])
                             : "r"(ad));
            }
            uint32_t bf[8][2];
#pragma unroll
            for (int ntp = 0; ntp < 4; ntp++) {
                int r = b_row + ntp * 16;
                uint32_t ad = base + 16384 + r * 128 + (((ks * 2 + b_ch) ^ (r & 7)) << 4);
                asm volatile("ldmatrix.sync.aligned.m8n8.x4.shared.b16 {%0,%1,%2,%3}, [%4];"
                             : "=r"(bf[ntp * 2][0]), "=r"(bf[ntp * 2][1]),
                               "=r"(bf[ntp * 2 + 1][0]), "=r"(bf[ntp * 2 + 1][1])
                             : "r"(ad));
            }
#pragma unroll
            for (int mt = 0; mt < 2; mt++)
#pragma unroll
                for (int nt = 0; nt < 8; nt++) {
                    asm volatile(
                        "mma.sync.aligned.m16n8k16.row.col.f32.f16.f16.f32 "
                        "{%0,%1,%2,%3}, {%4,%5,%6,%7}, {%8,%9}, {%0,%1,%2,%3};"
                        : "+f"(acc[mt][nt][0]), "+f"(acc[mt][nt][1]),
                          "+f"(acc[mt][nt][2]), "+f"(acc[mt][nt][3])
                        : "r"(af[mt][0]), "r"(af[mt][1]), "r"(af[mt][2]), "r"(af[mt][3]),
                          "r"(bf[nt][0]), "r"(bf[nt][1]));
                }
        }
        __syncthreads();
    }

#pragma unroll
    for (int mt = 0; mt < 2; mt++)
#pragma unroll
        for (int h2 = 0; h2 < 2; h2++) {
            int row = bm + wm * 32 + mt * 16 + (lane >> 2) + h2 * 8;
#pragma unroll
            for (int nt = 0; nt < 8; nt++) {
                int col = bn + wn * 64 + nt * 8 + (lane & 3) * 2;
                float2 o;
                o.x = acc[mt][nt][h2 * 2 + 0] + g_bcat[col + 0];
                o.y = acc[mt][nt][h2 * 2 + 1] + g_bcat[col + 1];
                *(float2*)&g_qkv[(size_t)row * GN + col] = o;
            }
        }
}

// ---------------- K2: pre = mask ? log(max(relu(PE@Wpos^T+bpos),1e-6))+lbias : -9e15+lbias ----
__global__ __launch_bounds__(128)
void pos_kernel(const float* __restrict__ PEmb, const float* __restrict__ Wpos,
                const float* __restrict__ bpos, const int* __restrict__ adj,
                const float* __restrict__ lbias) {
    __shared__ float pe[128 * 65];
    __shared__ float wpT[64 * 17];
    __shared__ float bp[16];
    int t = threadIdx.x;
    size_t base = (size_t)blockIdx.x * 128 * 64;
    for (int i = t; i < 128 * 64; i += 128)
        pe[(i >> 6) * 65 + (i & 63)] = PEmb[base + i];
    for (int i = t; i < 1024; i += 128)
        wpT[(i & 63) * 17 + (i >> 6)] = Wpos[i];
    if (t < 16) bp[t] = bpos[t];
    __syncthreads();

    float s[16];
#pragma unroll
    for (int h = 0; h < 16; h++) s[h] = 0.f;
    const float* pr = &pe[t * 65];
#pragma unroll 8
    for (int p = 0; p < 64; p++) {
        float a = pr[p];
        const float* w = &wpT[p * 17];
#pragma unroll
        for (int h = 0; h < 16; h++) s[h] += a * w[h];
    }
    int r = blockIdx.x * 128 + t;     // r = (b*36+n)*36 + m
    int bn = r / 36, m = r % 36;
    bool live = adj[r] > 0;
    float lb = lbias[r];
    size_t ob = (size_t)bn * 16 * 36 + m;
#pragma unroll
    for (int h = 0; h < 16; h++) {
        float v = fmaxf(s[h] + bp[h], 1e-6f);
        g_pre[ob + (size_t)h * 36] = (live ? __logf(v) : -9e15f) + lb;
    }
}

// ---------------- K3: attention per (b,h,half): 18 q-rows x 36 keys ----------------
__global__ __launch_bounds__(256, 4)
void attn_kernel(const float* __restrict__ bout, float* __restrict__ out) {
    __shared__ float qh[18][64];
    __shared__ float khT[64][40];
    __shared__ float vp[36][64];
    __shared__ float att[18][36];
    int b = blockIdx.x >> 5, h = (blockIdx.x >> 1) & 15, half = blockIdx.x & 1;
    int n_base = half * 18;
    int t = threadIdx.x;

    const float* base = g_qkv + (size_t)b * 36 * GN + h * 64;
    // load k (transposed), v (full 36), q (18 rows of this half)
    for (int i = t; i < 1440; i += 256) {
        if (i < 576) {
            int n = i >> 4, c = (i & 15) << 2;
            float4 k4 = *(const float4*)(base + (size_t)n * GN + 1024 + c);
            khT[c + 0][n] = k4.x; khT[c + 1][n] = k4.y;
            khT[c + 2][n] = k4.z; khT[c + 3][n] = k4.w;
        } else if (i < 1152) {
            int j = i - 576;
            int n = j >> 4, c = (j & 15) << 2;
            *(float4*)&vp[n][c] = *(const float4*)(base + (size_t)n * GN + 2048 + c);
        } else {
            int j = i - 1152;
            int n = j >> 4, c = (j & 15) << 2;
            *(float4*)&qh[n][c] = *(const float4*)(base + (size_t)(n_base + n) * GN + c);
        }
    }
    __syncthreads();

    // logits: 1n x 4m, 162 active threads; logit = q.k/8 + pre
    if (t < 162) {
        int n = t / 9, m0 = (t % 9) * 4;
        float4 s = make_float4(0.f, 0.f, 0.f, 0.f);
#pragma unroll 8
        for (int d = 0; d < 64; d++) {
            float a = qh[n][d];
            float4 kv = *(const float4*)&khT[d][m0];
            s.x += a * kv.x; s.y += a * kv.y; s.z += a * kv.z; s.w += a * kv.w;
        }
        const float* pr = g_pre + (size_t)(b * 36 + n_base + n) * 576 + h * 36 + m0;
        att[n][m0 + 0] = s.x * 0.125f + pr[0];
        att[n][m0 + 1] = s.y * 0.125f + pr[1];
        att[n][m0 + 2] = s.z * 0.125f + pr[2];
        att[n][m0 + 3] = s.w * 0.125f + pr[3];
    }
    __syncthreads();

    // softmax over 36 (one warp per row, 18 rows)
    int warp = t >> 5, lane = t & 31;
    for (int n = warp; n < 18; n += 8) {
        float x1 = att[n][lane];
        float x2 = (lane < 4) ? att[n][32 + lane] : -3e38f;
        float mx = fmaxf(x1, x2);
#pragma unroll
        for (int off = 16; off > 0; off >>= 1)
            mx = fmaxf(mx, __shfl_xor_sync(0xffffffffu, mx, off));
        float e1 = __expf(x1 - mx);
        float e2 = (lane < 4) ? __expf(x2 - mx) : 0.f;
        float sum = e1 + e2;
#pragma unroll
        for (int off = 16; off > 0; off >>= 1)
            sum += __shfl_xor_sync(0xffffffffu, sum, off);
        float inv = 1.f / sum;
        att[n][lane] = e1 * inv;
        if (lane < 4) att[n][32 + lane] = e2 * inv;
    }
    __syncthreads();

    // out = att @ vp + bout : 1n x 8e, 144 active threads
    const float* bo = bout + h * 64;
    if (t < 144) {
        int n = t / 8, e0 = (t % 8) * 8;
        float4 aa = *(const float4*)&bo[e0];
        float4 ab = *(const float4*)&bo[e0 + 4];
#pragma unroll 6
        for (int m = 0; m < 36; m++) {
            float w = att[n][m];
            float4 va = *(const float4*)&vp[m][e0];
            float4 vb = *(const float4*)&vp[m][e0 + 4];
            aa.x += w * va.x; aa.y += w * va.y; aa.z += w * va.z; aa.w += w * va.w;
            ab.x += w * vb.x; ab.y += w * vb.y; ab.z += w * vb.z; ab.w += w * vb.w;
        }
        float* o = &out[(size_t)(b * 36 + n_base + n) * 1024 + h * 64 + e0];
        *(float4*)o = aa; *(float4*)(o + 4) = ab;
    }
}

// ---------------- launch: fork/join DAG over side streams ----------------
extern "C" void kernel_launch(void* const* d_in, const int* in_sizes, int n_in,
                              void* d_out, int out_size) {
    const float* roi  = (const float*)d_in[0];
    const int*   adj  = (const int*)  d_in[1];
    const float* pe   = (const float*)d_in[2];
    const float* lb   = (const float*)d_in[3];
    const float* Wq   = (const float*)d_in[4];
    const float* bq   = (const float*)d_in[5];
    const float* Wk   = (const float*)d_in[6];
    const float* bk   = (const float*)d_in[7];
    const float* Wpos = (const float*)d_in[8];
    const float* bpos = (const float*)d_in[9];
    const float* Wout = (const float*)d_in[10];
    const float* bout = (const float*)d_in[11];
    float* out = (float*)d_out;

    static int inited = 0;
    static cudaStream_t s1, s2;
    static cudaEvent_t eFork, eW, ePos;
    if (!inited) {
        cudaFuncSetAttribute(gemm_hmma, cudaFuncAttributeMaxDynamicSharedMemorySize,
                             NSTAGE * STG);
        cudaStreamCreateWithFlags(&s1, cudaStreamNonBlocking);
        cudaStreamCreateWithFlags(&s2, cudaStreamNonBlocking);
        cudaEventCreateWithFlags(&eFork, cudaEventDisableTiming);
        cudaEventCreateWithFlags(&eW, cudaEventDisableTiming);
        cudaEventCreateWithFlags(&ePos, cudaEventDisableTiming);
        inited = 1;
    }

    // fork side streams off the (captured) legacy stream
    cudaEventRecord(eFork, 0);
    cudaStreamWaitEvent(s1, eFork, 0);
    cudaStreamWaitEvent(s2, eFork, 0);

    // s1: weight conversion + bias pack (needed by gemm)
    conv_B<<<GN * GK / 4 / 256, 256, 0, s1>>>(Wq, Wk, Wout);
    fill_bcat<<<GN / 256, 256, 0, s1>>>(bq, bk);
    cudaEventRecord(eW, s1);

    // s2: pos MLP + mask/bias prefold (needed only by attn) — overlaps conv_A + gemm
    pos_kernel<<<(4608 * 36) / 128, 128, 0, s2>>>(pe, Wpos, bpos, adj, lb);
    cudaEventRecord(ePos, s2);

    // main stream: A conversion, then gemm (after weights ready)
    conv_A<<<GM * GK / 4 / 256, 256>>>(roi);
    cudaStreamWaitEvent(0, eW, 0);

    dim3 gg(GN / BN, GM / BM);
    gemm_hmma<<<gg, 256, NSTAGE * STG>>>();

    // attn after gemm (stream order) and pos (event)
    cudaStreamWaitEvent(0, ePos, 0);
    attn_kernel<<<128 * 16 * 2, 256>>>(bout, out);
}

// round 12
// speedup vs baseline: 1.1931x; 1.1931x over previous
#include <cuda_runtime.h>
#include <cuda_fp16.h>
#include <math.h>
#include <cstdint>

// B=128, N=NONGT=36, D=1024, H=16, DG=64, PE=64
#define GM 4608      // rows = B*N
#define GN 3072      // cols = 3*1024  [q|k|vproj]
#define GK 1024      // inner dim
#define KP 1024      // fp16 K (single term Ah @ Bh)
#define BM 128
#define BN 128
#define BK 64
#define NK (KP / BK)   // 16
#define STG 32768      // stage stride: A 16KB + B 16KB
#define NSTAGE 3

// ---------------- device scratch ----------------
__device__ __align__(16) __half g_Ah[(size_t)GM * KP];   // 9.4 MB
__device__ __align__(16) __half g_Bh[(size_t)GN * KP];   // 6.3 MB  [N,K] K-major
__device__ __align__(16) float g_bcat[GN];
__device__ __align__(16) float g_qkv[(size_t)GM * GN];   // 56.6 MB
__device__ __align__(16) float g_pre[4608 * 16 * 36];    // 10.6 MB  pre[b,n][h][m]

// ---------------- helpers ----------------
__device__ __forceinline__ uint32_t smem_u32(const void* p) {
    uint32_t a;
    asm("{ .reg .u64 t; cvta.to.shared.u64 t, %1; cvt.u32.u64 %0, t; }" : "=r"(a) : "l"(p));
    return a;
}
__device__ __forceinline__ void cp16(uint32_t d, const void* s) {
    asm volatile("cp.async.cg.shared.global [%0], [%1], 16;" :: "r"(d), "l"(s));
}

// ---------------- K0a: A fp32 -> fp16 ----------------
__global__ __launch_bounds__(256) void conv_A(const float* __restrict__ A) {
    int i = blockIdx.x * 256 + threadIdx.x;
    float4 v = ((const float4*)A)[i];
    __half2 h01 = __halves2half2(__float2half_rn(v.x), __float2half_rn(v.y));
    __half2 h23 = __halves2half2(__float2half_rn(v.z), __float2half_rn(v.w));
    size_t base = (size_t)i * 4;
    *(__half2*)&g_Ah[base] = h01; *(__half2*)&g_Ah[base + 2] = h23;
}

// ---------------- K0b: weights -> fp16 ----------------
__global__ __launch_bounds__(256) void conv_B(const float* __restrict__ Wq,
                                              const float* __restrict__ Wk,
                                              const float* __restrict__ Wout) {
    int i = blockIdx.x * 256 + threadIdx.x;
    int row = i >> 8;
    int c4 = (i & 255) << 2;
    const float* src = (row < 1024) ? (Wq + (size_t)row * 1024)
                     : (row < 2048) ? (Wk + (size_t)(row - 1024) * 1024)
                                    : (Wout + (size_t)(row - 2048) * 1024);
    float4 v = *(const float4*)(src + c4);
    __half2 h01 = __halves2half2(__float2half_rn(v.x), __float2half_rn(v.y));
    __half2 h23 = __halves2half2(__float2half_rn(v.z), __float2half_rn(v.w));
    size_t base = (size_t)row * KP + c4;
    *(__half2*)&g_Bh[base] = h01; *(__half2*)&g_Bh[base + 2] = h23;
}

__global__ void fill_bcat(const float* __restrict__ bq, const float* __restrict__ bk) {
    int n = blockIdx.x * 256 + threadIdx.x;
    float v = 0.f;
    if (n < 1024) v = bq[n];
    else if (n < 2048) v = bk[n - 1024];
    g_bcat[n] = v;
}

// ---------------- K1: HMMA GEMM  qkv = A @ B^T + bcat ----------------
__device__ __forceinline__ void load_tile(uint32_t base, const __half* Ag, const __half* Bg, int t) {
#pragma unroll
    for (int i = 0; i < 4; i++) {
        int u = t + i * 256;
        int row = u >> 3, k = u & 7;
        uint32_t sw = row * 128 + ((k ^ (row & 7)) << 4);
        cp16(base + sw, (const char*)(Ag + (size_t)row * KP) + k * 16);
        cp16(base + 16384 + sw, (const char*)(Bg + (size_t)row * KP) + k * 16);
    }
    asm volatile("cp.async.commit_group;" ::: "memory");
}

__global__ __launch_bounds__(256, 2) void gemm_hmma() {
    extern __shared__ char smem[];
    uint32_t sb = smem_u32(smem);
    int t = threadIdx.x, lane = t & 31, wid = t >> 5;
    int bm = blockIdx.y * BM, bn = blockIdx.x * BN;
    int wm = wid >> 1, wn = wid & 1;

    const __half* Ag = g_Ah + (size_t)bm * KP;
    const __half* Bg = g_Bh + (size_t)bn * KP;

    float acc[2][8][4];
#pragma unroll
    for (int mt = 0; mt < 2; mt++)
#pragma unroll
        for (int nt = 0; nt < 8; nt++)
#pragma unroll
            for (int j = 0; j < 4; j++) acc[mt][nt][j] = 0.f;

    int a_row = wm * 32 + (lane & 7) + ((lane >> 3) & 1) * 8;   // + mt*16
    int a_ch  = (lane >> 4);                                     // + ks*2
    int b_row = wn * 64 + (lane & 7) + ((lane >> 4) & 1) * 8;   // + ntp*16
    int b_ch  = (lane >> 3) & 1;                                 // + ks*2

    load_tile(sb, Ag, Bg, t);
    load_tile(sb + STG, Ag + BK, Bg + BK, t);

    for (int kt = 0; kt < NK; kt++) {
        if (kt + 2 < NK) {
            load_tile(sb + ((kt + 2) % NSTAGE) * STG,
                      Ag + (size_t)(kt + 2) * BK, Bg + (size_t)(kt + 2) * BK, t);
            asm volatile("cp.async.wait_group 2;" ::: "memory");
        } else {
            asm volatile("cp.async.wait_group 0;" ::: "memory");
        }
        __syncthreads();

        uint32_t base = sb + (kt % NSTAGE) * STG;
#pragma unroll
        for (int ks = 0; ks < 4; ks++) {
            uint32_t af[2][4];
#pragma unroll
            for (int mt = 0; mt < 2; mt++) {
                int r = a_row + mt * 16;
                uint32_t ad = base + r * 128 + (((ks * 2 + a_ch) ^ (r & 7)) << 4);
                asm volatile("ldmatrix.sync.aligned.m8n8.x4.shared.b16 {%0,%1,%2,%3}, [%4];"
                             : "=r"(af[mt][0]), "=r"(af[mt][1]), "=r"(af[mt][2]), "=r"(af[mt][3])
                             : "r"(ad));
            }
            uint32_t bf[8][2];
#pragma unroll
            for (int ntp = 0; ntp < 4; ntp++) {
                int r = b_row + ntp * 16;
                uint32_t ad = base + 16384 + r * 128 + (((ks * 2 + b_ch) ^ (r & 7)) << 4);
                asm volatile("ldmatrix.sync.aligned.m8n8.x4.shared.b16 {%0,%1,%2,%3}, [%4];"
                             : "=r"(bf[ntp * 2][0]), "=r"(bf[ntp * 2][1]),
                               "=r"(bf[ntp * 2 + 1][0]), "=r"(bf[ntp * 2 + 1][1])
                             : "r"(ad));
            }
#pragma unroll
            for (int mt = 0; mt < 2; mt++)
#pragma unroll
                for (int nt = 0; nt < 8; nt++) {
                    asm volatile(
                        "mma.sync.aligned.m16n8k16.row.col.f32.f16.f16.f32 "
                        "{%0,%1,%2,%3}, {%4,%5,%6,%7}, {%8,%9}, {%0,%1,%2,%3};"
                        : "+f"(acc[mt][nt][0]), "+f"(acc[mt][nt][1]),
                          "+f"(acc[mt][nt][2]), "+f"(acc[mt][nt][3])
                        : "r"(af[mt][0]), "r"(af[mt][1]), "r"(af[mt][2]), "r"(af[mt][3]),
                          "r"(bf[nt][0]), "r"(bf[nt][1]));
                }
        }
        __syncthreads();
    }

#pragma unroll
    for (int mt = 0; mt < 2; mt++)
#pragma unroll
        for (int h2 = 0; h2 < 2; h2++) {
            int row = bm + wm * 32 + mt * 16 + (lane >> 2) + h2 * 8;
#pragma unroll
            for (int nt = 0; nt < 8; nt++) {
                int col = bn + wn * 64 + nt * 8 + (lane & 3) * 2;
                float2 o;
                o.x = acc[mt][nt][h2 * 2 + 0] + g_bcat[col + 0];
                o.y = acc[mt][nt][h2 * 2 + 1] + g_bcat[col + 1];
                *(float2*)&g_qkv[(size_t)row * GN + col] = o;
            }
        }
}

// ---------------- K2: pre = (mask ? log(max(relu(PE@Wpos^T+bpos),1e-6)) : -9e15) + lbias ----
__global__ __launch_bounds__(128)
void pos_kernel(const float* __restrict__ PEmb, const float* __restrict__ Wpos,
                const float* __restrict__ bpos, const int* __restrict__ adj,
                const float* __restrict__ lbias) {
    __shared__ float pe[128 * 65];
    __shared__ float wpT[64 * 17];
    __shared__ float bp[16];
    int t = threadIdx.x;
    size_t base = (size_t)blockIdx.x * 128 * 64;
    for (int i = t; i < 128 * 64; i += 128)
        pe[(i >> 6) * 65 + (i & 63)] = PEmb[base + i];
    for (int i = t; i < 1024; i += 128)
        wpT[(i & 63) * 17 + (i >> 6)] = Wpos[i];
    if (t < 16) bp[t] = bpos[t];
    __syncthreads();

    float s[16];
#pragma unroll
    for (int h = 0; h < 16; h++) s[h] = 0.f;
    const float* pr = &pe[t * 65];
#pragma unroll 8
    for (int p = 0; p < 64; p++) {
        float a = pr[p];
        const float* w = &wpT[p * 17];
#pragma unroll
        for (int h = 0; h < 16; h++) s[h] += a * w[h];
    }
    int r = blockIdx.x * 128 + t;     // r = (b*36+n)*36 + m
    int bn = r / 36, m = r % 36;
    bool live = adj[r] > 0;
    float lb = lbias[r];
    size_t ob = (size_t)bn * 16 * 36 + m;
#pragma unroll
    for (int h = 0; h < 16; h++) {
        float v = fmaxf(s[h] + bp[h], 1e-6f);
        g_pre[ob + (size_t)h * 36] = (live ? __logf(v) : -9e15f) + lb;
    }
}

// ---------------- K3: attention per (b,h) ----------------
__global__ __launch_bounds__(256, 4)
void attn_kernel(const float* __restrict__ bout, float* __restrict__ out) {
    __shared__ float qh[36][64];
    __shared__ float khT[64][40];
    __shared__ float vp[36][64];
    __shared__ float att[36 * 36];
    int b = blockIdx.x >> 4, h = blockIdx.x & 15;
    int t = threadIdx.x;

    const float* base = g_qkv + (size_t)b * 36 * GN + h * 64;
    for (int i = t; i < 576; i += 256) {
        int n = i >> 4, c = (i & 15) << 2;
        const float* rp = base + (size_t)n * GN + c;
        float4 q4 = *(const float4*)rp;
        float4 k4 = *(const float4*)(rp + 1024);
        float4 v4 = *(const float4*)(rp + 2048);
        *(float4*)&qh[n][c] = q4;
        khT[c + 0][n] = k4.x; khT[c + 1][n] = k4.y;
        khT[c + 2][n] = k4.z; khT[c + 3][n] = k4.w;
        *(float4*)&vp[n][c] = v4;
    }
    __syncthreads();

    // logits: 2n x 4m register tile, 162 active threads; logit = q.k/8 + pre
    const float* pl = g_pre + (size_t)b * 36 * 576 + h * 36;
    if (t < 162) {
        int n0 = (t / 9) * 2, m0 = (t % 9) * 4;
        float4 s0 = make_float4(0.f, 0.f, 0.f, 0.f);
        float4 s1 = make_float4(0.f, 0.f, 0.f, 0.f);
#pragma unroll 8
        for (int d = 0; d < 64; d++) {
            float a0 = qh[n0][d], a1 = qh[n0 + 1][d];
            float4 kv = *(const float4*)&khT[d][m0];
            s0.x += a0 * kv.x; s0.y += a0 * kv.y; s0.z += a0 * kv.z; s0.w += a0 * kv.w;
            s1.x += a1 * kv.x; s1.y += a1 * kv.y; s1.z += a1 * kv.z; s1.w += a1 * kv.w;
        }
        const float* p0 = pl + (size_t)n0 * 576 + m0;
        const float* p1 = p0 + 576;
        att[n0 * 36 + m0 + 0] = s0.x * 0.125f + p0[0];
        att[n0 * 36 + m0 + 1] = s0.y * 0.125f + p0[1];
        att[n0 * 36 + m0 + 2] = s0.z * 0.125f + p0[2];
        att[n0 * 36 + m0 + 3] = s0.w * 0.125f + p0[3];
        att[(n0 + 1) * 36 + m0 + 0] = s1.x * 0.125f + p1[0];
        att[(n0 + 1) * 36 + m0 + 1] = s1.y * 0.125f + p1[1];
        att[(n0 + 1) * 36 + m0 + 2] = s1.z * 0.125f + p1[2];
        att[(n0 + 1) * 36 + m0 + 3] = s1.w * 0.125f + p1[3];
    }
    __syncthreads();

    // softmax over 36 (one warp per row)
    int warp = t >> 5, lane = t & 31;
    for (int n = warp; n < 36; n += 8) {
        float x1 = att[n * 36 + lane];
        float x2 = (lane < 4) ? att[n * 36 + 32 + lane] : -3e38f;
        float mx = fmaxf(x1, x2);
#pragma unroll
        for (int off = 16; off > 0; off >>= 1)
            mx = fmaxf(mx, __shfl_xor_sync(0xffffffffu, mx, off));
        float e1 = __expf(x1 - mx);
        float e2 = (lane < 4) ? __expf(x2 - mx) : 0.f;
        float sum = e1 + e2;
#pragma unroll
        for (int off = 16; off > 0; off >>= 1)
            sum += __shfl_xor_sync(0xffffffffu, sum, off);
        float inv = 1.f / sum;
        att[n * 36 + lane] = e1 * inv;
        if (lane < 4) att[n * 36 + 32 + lane] = e2 * inv;
    }
    __syncthreads();

    // out = att @ vp + bout : 2n x 8e register tile, 144 active threads
    const float* bo = bout + h * 64;
    if (t < 144) {
        int n0 = (t / 8) * 2, e0 = (t % 8) * 8;
        float4 a0a = *(const float4*)&bo[e0];
        float4 a0b = *(const float4*)&bo[e0 + 4];
        float4 a1a = a0a, a1b = a0b;
#pragma unroll 6
        for (int m = 0; m < 36; m++) {
            float w0 = att[n0 * 36 + m], w1 = att[(n0 + 1) * 36 + m];
            float4 va = *(const float4*)&vp[m][e0];
            float4 vb = *(const float4*)&vp[m][e0 + 4];
            a0a.x += w0 * va.x; a0a.y += w0 * va.y; a0a.z += w0 * va.z; a0a.w += w0 * va.w;
            a0b.x += w0 * vb.x; a0b.y += w0 * vb.y; a0b.z += w0 * vb.z; a0b.w += w0 * vb.w;
            a1a.x += w1 * va.x; a1a.y += w1 * va.y; a1a.z += w1 * va.z; a1a.w += w1 * va.w;
            a1b.x += w1 * vb.x; a1b.y += w1 * vb.y; a1b.z += w1 * vb.z; a1b.w += w1 * vb.w;
        }
        float* o0 = &out[(size_t)(b * 36 + n0) * 1024 + h * 64 + e0];
        *(float4*)o0 = a0a; *(float4*)(o0 + 4) = a0b;
        float* o1 = o0 + 1024;
        *(float4*)o1 = a1a; *(float4*)(o1 + 4) = a1b;
    }
}

// ---------------- launch: fork/join DAG over side streams ----------------
extern "C" void kernel_launch(void* const* d_in, const int* in_sizes, int n_in,
                              void* d_out, int out_size) {
    const float* roi  = (const float*)d_in[0];
    const int*   adj  = (const int*)  d_in[1];
    const float* pe   = (const float*)d_in[2];
    const float* lb   = (const float*)d_in[3];
    const float* Wq   = (const float*)d_in[4];
    const float* bq   = (const float*)d_in[5];
    const float* Wk   = (const float*)d_in[6];
    const float* bk   = (const float*)d_in[7];
    const float* Wpos = (const float*)d_in[8];
    const float* bpos = (const float*)d_in[9];
    const float* Wout = (const float*)d_in[10];
    const float* bout = (const float*)d_in[11];
    float* out = (float*)d_out;

    static int inited = 0;
    static cudaStream_t s1, s2;
    static cudaEvent_t eFork, eW, ePos;
    if (!inited) {
        cudaFuncSetAttribute(gemm_hmma, cudaFuncAttributeMaxDynamicSharedMemorySize,
                             NSTAGE * STG);
        cudaStreamCreateWithFlags(&s1, cudaStreamNonBlocking);
        cudaStreamCreateWithFlags(&s2, cudaStreamNonBlocking);
        cudaEventCreateWithFlags(&eFork, cudaEventDisableTiming);
        cudaEventCreateWithFlags(&eW, cudaEventDisableTiming);
        cudaEventCreateWithFlags(&ePos, cudaEventDisableTiming);
        inited = 1;
    }

    // fork side streams off the (captured) legacy stream
    cudaEventRecord(eFork, 0);
    cudaStreamWaitEvent(s1, eFork, 0);
    cudaStreamWaitEvent(s2, eFork, 0);

    // s1: weight conversion + bias pack (needed by gemm)
    conv_B<<<GN * GK / 4 / 256, 256, 0, s1>>>(Wq, Wk, Wout);
    fill_bcat<<<GN / 256, 256, 0, s1>>>(bq, bk);
    cudaEventRecord(eW, s1);

    // s2: pos MLP + mask/bias prefold (needed only by attn) — overlaps conv_A + gemm
    pos_kernel<<<(4608 * 36) / 128, 128, 0, s2>>>(pe, Wpos, bpos, adj, lb);
    cudaEventRecord(ePos, s2);

    // main stream: A conversion, then gemm (after weights ready)
    conv_A<<<GM * GK / 4 / 256, 256>>>(roi);
    cudaStreamWaitEvent(0, eW, 0);

    dim3 gg(GN / BN, GM / BM);
    gemm_hmma<<<gg, 256, NSTAGE * STG>>>();

    // attn after gemm (stream order) and pos (event)
    cudaStreamWaitEvent(0, ePos, 0);
    attn_kernel<<<128 * 16, 256>>>(bout, out);
}

// round 13
// speedup vs baseline: 1.2469x; 1.0451x over previous
#include <cuda_runtime.h>
#include <cuda_fp16.h>
#include <math.h>
#include <cstdint>

// B=128, N=NONGT=36, D=1024, H=16, DG=64, PE=64
#define GM 4608      // rows = B*N
#define GN 3072      // cols = 3*1024  [q|k|vproj]
#define GK 1024      // inner dim
#define KP 1024      // fp16 K (single term Ah @ Bh)
#define BM 128
#define BN 128
#define BK 64
#define NK (KP / BK)   // 16
#define STG 32768      // stage stride: A 16KB + B 16KB
#define NSTAGE 3

// ---------------- device scratch ----------------
__device__ __align__(16) __half g_Ah[(size_t)GM * KP];   // 9.4 MB
__device__ __align__(16) __half g_Bh[(size_t)GN * KP];   // 6.3 MB  [N,K] K-major
__device__ __align__(16) float g_bcat[GN];
__device__ __align__(16) float g_qkv[(size_t)GM * GN];   // 56.6 MB
__device__ __align__(16) float g_pre[4608 * 16 * 36];    // 10.6 MB  pre[b,n][h][m]

// ---------------- helpers ----------------
__device__ __forceinline__ uint32_t smem_u32(const void* p) {
    uint32_t a;
    asm("{ .reg .u64 t; cvta.to.shared.u64 t, %1; cvt.u32.u64 %0, t; }" : "=r"(a) : "l"(p));
    return a;
}
__device__ __forceinline__ void cp16(uint32_t d, const void* s) {
    asm volatile("cp.async.cg.shared.global [%0], [%1], 16;" :: "r"(d), "l"(s));
}

// ---------------- K0a: A fp32 -> fp16 ----------------
__global__ __launch_bounds__(256) void conv_A(const float* __restrict__ A) {
    int i = blockIdx.x * 256 + threadIdx.x;
    float4 v = ((const float4*)A)[i];
    __half2 h01 = __halves2half2(__float2half_rn(v.x), __float2half_rn(v.y));
    __half2 h23 = __halves2half2(__float2half_rn(v.z), __float2half_rn(v.w));
    size_t base = (size_t)i * 4;
    *(__half2*)&g_Ah[base] = h01; *(__half2*)&g_Ah[base + 2] = h23;
}

// ---------------- K0b: weights -> fp16 ----------------
__global__ __launch_bounds__(256) void conv_B(const float* __restrict__ Wq,
                                              const float* __restrict__ Wk,
                                              const float* __restrict__ Wout) {
    int i = blockIdx.x * 256 + threadIdx.x;
    int row = i >> 8;
    int c4 = (i & 255) << 2;
    const float* src = (row < 1024) ? (Wq + (size_t)row * 1024)
                     : (row < 2048) ? (Wk + (size_t)(row - 1024) * 1024)
                                    : (Wout + (size_t)(row - 2048) * 1024);
    float4 v = *(const float4*)(src + c4);
    __half2 h01 = __halves2half2(__float2half_rn(v.x), __float2half_rn(v.y));
    __half2 h23 = __halves2half2(__float2half_rn(v.z), __float2half_rn(v.w));
    size_t base = (size_t)row * KP + c4;
    *(__half2*)&g_Bh[base] = h01; *(__half2*)&g_Bh[base + 2] = h23;
}

__global__ void fill_bcat(const float* __restrict__ bq, const float* __restrict__ bk) {
    int n = blockIdx.x * 256 + threadIdx.x;
    float v = 0.f;
    if (n < 1024) v = bq[n];
    else if (n < 2048) v = bk[n - 1024];
    g_bcat[n] = v;
}

// ---------------- K1: HMMA GEMM  qkv = A @ B^T + bcat ----------------
__device__ __forceinline__ void load_tile(uint32_t base, const __half* Ag, const __half* Bg, int t) {
#pragma unroll
    for (int i = 0; i < 4; i++) {
        int u = t + i * 256;
        int row = u >> 3, k = u & 7;
        uint32_t sw = row * 128 + ((k ^ (row & 7)) << 4);
        cp16(base + sw, (const char*)(Ag + (size_t)row * KP) + k * 16);
        cp16(base + 16384 + sw, (const char*)(Bg + (size_t)row * KP) + k * 16);
    }
    asm volatile("cp.async.commit_group;" ::: "memory");
}

__global__ __launch_bounds__(256, 2) void gemm_hmma() {
    extern __shared__ char smem[];
    uint32_t sb = smem_u32(smem);
    int t = threadIdx.x, lane = t & 31, wid = t >> 5;
    int bm = blockIdx.y * BM, bn = blockIdx.x * BN;
    int wm = wid >> 1, wn = wid & 1;

    const __half* Ag = g_Ah + (size_t)bm * KP;
    const __half* Bg = g_Bh + (size_t)bn * KP;

    float acc[2][8][4];
#pragma unroll
    for (int mt = 0; mt < 2; mt++)
#pragma unroll
        for (int nt = 0; nt < 8; nt++)
#pragma unroll
            for (int j = 0; j < 4; j++) acc[mt][nt][j] = 0.f;

    int a_row = wm * 32 + (lane & 7) + ((lane >> 3) & 1) * 8;   // + mt*16
    int a_ch  = (lane >> 4);                                     // + ks*2
    int b_row = wn * 64 + (lane & 7) + ((lane >> 4) & 1) * 8;   // + ntp*16
    int b_ch  = (lane >> 3) & 1;                                 // + ks*2

    load_tile(sb, Ag, Bg, t);
    load_tile(sb + STG, Ag + BK, Bg + BK, t);

    for (int kt = 0; kt < NK; kt++) {
        // wait for stage kt to land; single barrier per iteration
        if (kt + 1 < NK)
            asm volatile("cp.async.wait_group 1;" ::: "memory");
        else
            asm volatile("cp.async.wait_group 0;" ::: "memory");
        __syncthreads();
        // after the barrier, all warps are done reading stage (kt-1)%3 — safe to refill
        if (kt + 2 < NK)
            load_tile(sb + ((kt + 2) % NSTAGE) * STG,
                      Ag + (size_t)(kt + 2) * BK, Bg + (size_t)(kt + 2) * BK, t);

        uint32_t base = sb + (kt % NSTAGE) * STG;
#pragma unroll
        for (int ks = 0; ks < 4; ks++) {
            uint32_t af[2][4];
#pragma unroll
            for (int mt = 0; mt < 2; mt++) {
                int r = a_row + mt * 16;
                uint32_t ad = base + r * 128 + (((ks * 2 + a_ch) ^ (r & 7)) << 4);
                asm volatile("ldmatrix.sync.aligned.m8n8.x4.shared.b16 {%0,%1,%2,%3}, [%4];"
                             : "=r"(af[mt][0]), "=r"(af[mt][1]), "=r"(af[mt][2]), "=r"(af[mt][3])
                             : "r"(ad));
            }
            uint32_t bf[8][2];
#pragma unroll
            for (int ntp = 0; ntp < 4; ntp++) {
                int r = b_row + ntp * 16;
                uint32_t ad = base + 16384 + r * 128 + (((ks * 2 + b_ch) ^ (r & 7)) << 4);
                asm volatile("ldmatrix.sync.aligned.m8n8.x4.shared.b16 {%0,%1,%2,%3}, [%4];"
                             : "=r"(bf[ntp * 2][0]), "=r"(bf[ntp * 2][1]),
                               "=r"(bf[ntp * 2 + 1][0]), "=r"(bf[ntp * 2 + 1][1])
                             : "r"(ad));
            }
#pragma unroll
            for (int mt = 0; mt < 2; mt++)
#pragma unroll
                for (int nt = 0; nt < 8; nt++) {
                    asm volatile(
                        "mma.sync.aligned.m16n8k16.row.col.f32.f16.f16.f32 "
                        "{%0,%1,%2,%3}, {%4,%5,%6,%7}, {%8,%9}, {%0,%1,%2,%3};"
                        : "+f"(acc[mt][nt][0]), "+f"(acc[mt][nt][1]),
                          "+f"(acc[mt][nt][2]), "+f"(acc[mt][nt][3])
                        : "r"(af[mt][0]), "r"(af[mt][1]), "r"(af[mt][2]), "r"(af[mt][3]),
                          "r"(bf[nt][0]), "r"(bf[nt][1]));
                }
        }
    }

#pragma unroll
    for (int mt = 0; mt < 2; mt++)
#pragma unroll
        for (int h2 = 0; h2 < 2; h2++) {
            int row = bm + wm * 32 + mt * 16 + (lane >> 2) + h2 * 8;
#pragma unroll
            for (int nt = 0; nt < 8; nt++) {
                int col = bn + wn * 64 + nt * 8 + (lane & 3) * 2;
                float2 o;
                o.x = acc[mt][nt][h2 * 2 + 0] + g_bcat[col + 0];
                o.y = acc[mt][nt][h2 * 2 + 1] + g_bcat[col + 1];
                *(float2*)&g_qkv[(size_t)row * GN + col] = o;
            }
        }
}

// ---------------- K2: pre = (mask ? log(max(relu(PE@Wpos^T+bpos),1e-6)) : -9e15) + lbias ----
__global__ __launch_bounds__(128)
void pos_kernel(const float* __restrict__ PEmb, const float* __restrict__ Wpos,
                const float* __restrict__ bpos, const int* __restrict__ adj,
                const float* __restrict__ lbias) {
    __shared__ float pe[128 * 65];
    __shared__ float wpT[64 * 17];
    __shared__ float bp[16];
    int t = threadIdx.x;
    size_t base = (size_t)blockIdx.x * 128 * 64;
    for (int i = t; i < 128 * 64; i += 128)
        pe[(i >> 6) * 65 + (i & 63)] = PEmb[base + i];
    for (int i = t; i < 1024; i += 128)
        wpT[(i & 63) * 17 + (i >> 6)] = Wpos[i];
    if (t < 16) bp[t] = bpos[t];
    __syncthreads();

    float s[16];
#pragma unroll
    for (int h = 0; h < 16; h++) s[h] = 0.f;
    const float* pr = &pe[t * 65];
#pragma unroll 8
    for (int p = 0; p < 64; p++) {
        float a = pr[p];
        const float* w = &wpT[p * 17];
#pragma unroll
        for (int h = 0; h < 16; h++) s[h] += a * w[h];
    }
    int r = blockIdx.x * 128 + t;     // r = (b*36+n)*36 + m
    int bn = r / 36, m = r % 36;
    bool live = adj[r] > 0;
    float lb = lbias[r];
    size_t ob = (size_t)bn * 16 * 36 + m;
#pragma unroll
    for (int h = 0; h < 16; h++) {
        float v = fmaxf(s[h] + bp[h], 1e-6f);
        g_pre[ob + (size_t)h * 36] = (live ? __logf(v) : -9e15f) + lb;
    }
}

// ---------------- K3: attention per (b,h) ----------------
// qh/vp rows padded to 68 floats: row stride 272B rotates banks by 4/row,
// killing the same-bank-for-all-rows conflict of stride-64 rows.
__global__ __launch_bounds__(256, 4)
void attn_kernel(const float* __restrict__ bout, float* __restrict__ out) {
    __shared__ float qh[36][68];
    __shared__ float khT[64][40];
    __shared__ float vp[36][68];
    __shared__ float att[36 * 36];
    int b = blockIdx.x >> 4, h = blockIdx.x & 15;
    int t = threadIdx.x;

    const float* base = g_qkv + (size_t)b * 36 * GN + h * 64;
    for (int i = t; i < 576; i += 256) {
        int n = i >> 4, c = (i & 15) << 2;
        const float* rp = base + (size_t)n * GN + c;
        float4 q4 = *(const float4*)rp;
        float4 k4 = *(const float4*)(rp + 1024);
        float4 v4 = *(const float4*)(rp + 2048);
        *(float4*)&qh[n][c] = q4;
        khT[c + 0][n] = k4.x; khT[c + 1][n] = k4.y;
        khT[c + 2][n] = k4.z; khT[c + 3][n] = k4.w;
        *(float4*)&vp[n][c] = v4;
    }
    __syncthreads();

    // logits: 2n x 4m register tile, 162 active threads; logit = q.k/8 + pre
    const float* pl = g_pre + (size_t)b * 36 * 576 + h * 36;
    if (t < 162) {
        int n0 = (t / 9) * 2, m0 = (t % 9) * 4;
        float4 s0 = make_float4(0.f, 0.f, 0.f, 0.f);
        float4 s1 = make_float4(0.f, 0.f, 0.f, 0.f);
#pragma unroll 8
        for (int d = 0; d < 64; d++) {
            float a0 = qh[n0][d], a1 = qh[n0 + 1][d];
            float4 kv = *(const float4*)&khT[d][m0];
            s0.x += a0 * kv.x; s0.y += a0 * kv.y; s0.z += a0 * kv.z; s0.w += a0 * kv.w;
            s1.x += a1 * kv.x; s1.y += a1 * kv.y; s1.z += a1 * kv.z; s1.w += a1 * kv.w;
        }
        const float* p0 = pl + (size_t)n0 * 576 + m0;
        const float* p1 = p0 + 576;
        att[n0 * 36 + m0 + 0] = s0.x * 0.125f + p0[0];
        att[n0 * 36 + m0 + 1] = s0.y * 0.125f + p0[1];
        att[n0 * 36 + m0 + 2] = s0.z * 0.125f + p0[2];
        att[n0 * 36 + m0 + 3] = s0.w * 0.125f + p0[3];
        att[(n0 + 1) * 36 + m0 + 0] = s1.x * 0.125f + p1[0];
        att[(n0 + 1) * 36 + m0 + 1] = s1.y * 0.125f + p1[1];
        att[(n0 + 1) * 36 + m0 + 2] = s1.z * 0.125f + p1[2];
        att[(n0 + 1) * 36 + m0 + 3] = s1.w * 0.125f + p1[3];
    }
    __syncthreads();

    // softmax over 36 (one warp per row)
    int warp = t >> 5, lane = t & 31;
    for (int n = warp; n < 36; n += 8) {
        float x1 = att[n * 36 + lane];
        float x2 = (lane < 4) ? att[n * 36 + 32 + lane] : -3e38f;
        float mx = fmaxf(x1, x2);
#pragma unroll
        for (int off = 16; off > 0; off >>= 1)
            mx = fmaxf(mx, __shfl_xor_sync(0xffffffffu, mx, off));
        float e1 = __expf(x1 - mx);
        float e2 = (lane < 4) ? __expf(x2 - mx) : 0.f;
        float sum = e1 + e2;
#pragma unroll
        for (int off = 16; off > 0; off >>= 1)
            sum += __shfl_xor_sync(0xffffffffu, sum, off);
        float inv = 1.f / sum;
        att[n * 36 + lane] = e1 * inv;
        if (lane < 4) att[n * 36 + 32 + lane] = e2 * inv;
    }
    __syncthreads();

    // out = att @ vp + bout : 2n x 8e register tile, 144 active threads
    const float* bo = bout + h * 64;
    if (t < 144) {
        int n0 = (t / 8) * 2, e0 = (t % 8) * 8;
        float4 a0a = *(const float4*)&bo[e0];
        float4 a0b = *(const float4*)&bo[e0 + 4];
        float4 a1a = a0a, a1b = a0b;
#pragma unroll 6
        for (int m = 0; m < 36; m++) {
            float w0 = att[n0 * 36 + m], w1 = att[(n0 + 1) * 36 + m];
            float4 va = *(const float4*)&vp[m][e0];
            float4 vb = *(const float4*)&vp[m][e0 + 4];
            a0a.x += w0 * va.x; a0a.y += w0 * va.y; a0a.z += w0 * va.z; a0a.w += w0 * va.w;
            a0b.x += w0 * vb.x; a0b.y += w0 * vb.y; a0b.z += w0 * vb.z; a0b.w += w0 * vb.w;
            a1a.x += w1 * va.x; a1a.y += w1 * va.y; a1a.z += w1 * va.z; a1a.w += w1 * va.w;
            a1b.x += w1 * vb.x; a1b.y += w1 * vb.y; a1b.z += w1 * vb.z; a1b.w += w1 * vb.w;
        }
        float* o0 = &out[(size_t)(b * 36 + n0) * 1024 + h * 64 + e0];
        *(float4*)o0 = a0a; *(float4*)(o0 + 4) = a0b;
        float* o1 = o0 + 1024;
        *(float4*)o1 = a1a; *(float4*)(o1 + 4) = a1b;
    }
}

// ---------------- launch: fork/join DAG over side streams ----------------
extern "C" void kernel_launch(void* const* d_in, const int* in_sizes, int n_in,
                              void* d_out, int out_size) {
    const float* roi  = (const float*)d_in[0];
    const int*   adj  = (const int*)  d_in[1];
    const float* pe   = (const float*)d_in[2];
    const float* lb   = (const float*)d_in[3];
    const float* Wq   = (const float*)d_in[4];
    const float* bq   = (const float*)d_in[5];
    const float* Wk   = (const float*)d_in[6];
    const float* bk   = (const float*)d_in[7];
    const float* Wpos = (const float*)d_in[8];
    const float* bpos = (const float*)d_in[9];
    const float* Wout = (const float*)d_in[10];
    const float* bout = (const float*)d_in[11];
    float* out = (float*)d_out;

    static int inited = 0;
    static cudaStream_t s1, s2;
    static cudaEvent_t eFork, eW, ePos;
    if (!inited) {
        cudaFuncSetAttribute(gemm_hmma, cudaFuncAttributeMaxDynamicSharedMemorySize,
                             NSTAGE * STG);
        cudaStreamCreateWithFlags(&s1, cudaStreamNonBlocking);
        cudaStreamCreateWithFlags(&s2, cudaStreamNonBlocking);
        cudaEventCreateWithFlags(&eFork, cudaEventDisableTiming);
        cudaEventCreateWithFlags(&eW, cudaEventDisableTiming);
        cudaEventCreateWithFlags(&ePos, cudaEventDisableTiming);
        inited = 1;
    }

    // fork side streams off the (captured) legacy stream
    cudaEventRecord(eFork, 0);
    cudaStreamWaitEvent(s1, eFork, 0);
    cudaStreamWaitEvent(s2, eFork, 0);

    // s1: weight conversion + bias pack (needed by gemm)
    conv_B<<<GN * GK / 4 / 256, 256, 0, s1>>>(Wq, Wk, Wout);
    fill_bcat<<<GN / 256, 256, 0, s1>>>(bq, bk);
    cudaEventRecord(eW, s1);

    // s2: pos MLP + mask/bias prefold (needed only by attn) — overlaps conv_A + gemm
    pos_kernel<<<(4608 * 36) / 128, 128, 0, s2>>>(pe, Wpos, bpos, adj, lb);
    cudaEventRecord(ePos, s2);

    // main stream: A conversion, then gemm (after weights ready)
    conv_A<<<GM * GK / 4 / 256, 256>>>(roi);
    cudaStreamWaitEvent(0, eW, 0);

    dim3 gg(GN / BN, GM / BM);
    gemm_hmma<<<gg, 256, NSTAGE * STG>>>();

    // attn after gemm (stream order) and pos (event)
    cudaStreamWaitEvent(0, ePos, 0);
    attn_kernel<<<128 * 16, 256>>>(bout, out);
}